// round 14
// baseline (speedup 1.0000x reference)
#include <cuda_runtime.h>
#include <cuda_fp16.h>
#include <cstdint>
#include <math.h>

// Problem constants
#define BB   2
#define LL   2048
#define DD   2048
#define NHQ  32
#define NHKV 8
#define HD   64
#define GRP  4

// ---------------------------------------------------------------------------
// Scratch (allocation-free rule: __device__ globals)
// ---------------------------------------------------------------------------
__device__ __half g_xh[BB * LL * DD];              // x fp16
__device__ __half g_wqt[NHQ * HD * DD];            // Wq^T [N][K]
__device__ __half g_wkt[NHKV * HD * DD];
__device__ __half g_wvt[NHKV * HD * DD];
__device__ __half g_wot[DD * NHQ * HD];
__device__ __half g_q[BB * LL * NHQ * HD];         // q fp16 (pre-scaled by log2e/8)
__device__ __half g_k[BB * LL * NHKV * HD];        // k fp16
__device__ __half g_vt[BB * NHKV * HD * LL];       // v fp16, [b][hk][d][L]
__device__ __half g_ctx[BB * LL * NHQ * HD];       // attention output fp16

// ---------------------------------------------------------------------------
// helpers
// ---------------------------------------------------------------------------
__device__ __forceinline__ void mma_f16(float* d, const uint32_t* a, const uint32_t* b) {
    asm volatile(
        "mma.sync.aligned.m16n8k16.row.col.f32.f16.f16.f32 "
        "{%0,%1,%2,%3}, {%4,%5,%6,%7}, {%8,%9}, {%0,%1,%2,%3};"
        : "+f"(d[0]), "+f"(d[1]), "+f"(d[2]), "+f"(d[3])
        : "r"(a[0]), "r"(a[1]), "r"(a[2]), "r"(a[3]), "r"(b[0]), "r"(b[1]));
}

// pack two f32 into one f16x2 register (lo = a, hi = b)
__device__ __forceinline__ uint32_t pack_h2(float a, float b) {
    uint32_t r;
    asm("cvt.rn.f16x2.f32 %0, %1, %2;" : "=r"(r) : "f"(b), "f"(a));
    return r;
}

// explicit fast exp2 (MUFU.EX2)
__device__ __forceinline__ float ex2f(float x) {
    float y;
    asm("ex2.approx.f32 %0, %1;" : "=f"(y) : "f"(x));
    return y;
}

// in-register 8x8 fp16 tile transpose (warp-collective)
__device__ __forceinline__ uint32_t movm_t(uint32_t a) {
    uint32_t d;
    asm("movmatrix.sync.aligned.m8n8.trans.b16 %0, %1;" : "=r"(d) : "r"(a));
    return d;
}

// ldmatrix x4: 4 8x8 fp16 tiles
__device__ __forceinline__ void ldsm_x4(uint32_t& r0, uint32_t& r1, uint32_t& r2,
                                        uint32_t& r3, uint32_t addr) {
    asm volatile("ldmatrix.sync.aligned.m8n8.x4.shared.b16 {%0,%1,%2,%3}, [%4];"
                 : "=r"(r0), "=r"(r1), "=r"(r2), "=r"(r3) : "r"(addr));
}

// ldmatrix x2
__device__ __forceinline__ void ldsm_x2(uint32_t& r0, uint32_t& r1, uint32_t addr) {
    asm volatile("ldmatrix.sync.aligned.m8n8.x2.shared.b16 {%0,%1}, [%2];"
                 : "=r"(r0), "=r"(r1) : "r"(addr));
}

__device__ __forceinline__ void cpasync16(uint32_t saddr, const void* g) {
    asm volatile("cp.async.cg.shared.global [%0], [%1], 16;\n" :: "r"(saddr), "l"(g) : "memory");
}
__device__ __forceinline__ void cp_commit() {
    asm volatile("cp.async.commit_group;\n" ::: "memory");
}
template <int N>
__device__ __forceinline__ void cp_wait() {
    asm volatile("cp.async.wait_group %0;\n" :: "n"(N) : "memory");
}

// ---------------------------------------------------------------------------
// prep: x -> fp16
// ---------------------------------------------------------------------------
__global__ __launch_bounds__(256) void cvt_h_kernel(
    const float* __restrict__ in, __half* __restrict__ out, int n)
{
    const int i = (blockIdx.x * 256 + threadIdx.x) * 4;
    if (i < n) {
        float4 v = *(const float4*)(in + i);
        uint32_t h0 = pack_h2(v.x, v.y);
        uint32_t h1 = pack_h2(v.z, v.w);
        *(uint32_t*)(out + i) = h0;
        *(uint32_t*)(out + i + 2) = h1;
    }
}

// ---------------------------------------------------------------------------
// prep: transpose W[K,N] -> WT[N,K] fp16 (z-dim selects tensor pair)
// ---------------------------------------------------------------------------
__global__ __launch_bounds__(256) void transpose_h_kernel(
    const float* __restrict__ W0, const float* __restrict__ W1,
    __half* __restrict__ T0, __half* __restrict__ T1, int K, int N)
{
    __shared__ float t[32][33];
    const float* W = blockIdx.z ? W1 : W0;
    __half* T = blockIdx.z ? T1 : T0;
    const int n0 = blockIdx.x * 32;
    const int k0 = blockIdx.y * 32;
    const int tx = threadIdx.x, ty = threadIdx.y;
#pragma unroll
    for (int i = 0; i < 4; i++)
        t[ty + i * 8][tx] = W[(long)(k0 + ty + i * 8) * N + n0 + tx];
    __syncthreads();
#pragma unroll
    for (int i = 0; i < 4; i++)
        T[(long)(n0 + ty + i * 8) * K + k0 + tx] = __float2half(t[tx][ty + i * 8]);
}

// ---------------------------------------------------------------------------
// fp16 tensor-core GEMM: C[M,N] = A[M,K] @ BT[N,K]^T + bias
// 128x128 tile, K-chunk 64, 3-stage cp.async, 256 threads, warp tile 64x32,
// 2 CTAs/SM. (Proven Round-12 config.)
// ---------------------------------------------------------------------------
#define GSTR    36                 // 32-bit words per row (32 data + 4 pad)
#define GTILE_W (128 * GSTR)       // 4608 words per operand tile
#define GSTAGE_W (2 * GTILE_W)     // 9216 words = 36 KB
#define GSMEM   (3 * GSTAGE_W * 4) // 110592 B

#define QSCALE 0.1803368867f       // 0.125 * log2(e)

__global__ __launch_bounds__(256, 2) void gemm_f16(
    const __half* __restrict__ A,
    const __half* __restrict__ Bq, const __half* __restrict__ Bk,
    const __half* __restrict__ Bv,
    const float* __restrict__ bias_q, const float* __restrict__ bias_k,
    const float* __restrict__ bias_v,
    __half* __restrict__ outq, __half* __restrict__ outk,
    __half* __restrict__ outvt, float* __restrict__ outf,
    int qkv_mode)
{
    extern __shared__ uint32_t smw[];
    const uint32_t smb = (uint32_t)__cvta_generic_to_shared(smw);

    int mode, bm, bn;
    if (qkv_mode) {
        const int bx = blockIdx.x;
        if (bx < 512)      { mode = 0; bn = (bx & 15) * 128; bm = (bx >> 4) * 128; }
        else if (bx < 640) { const int t = bx - 512; mode = 1; bn = (t & 3) * 128; bm = (t >> 2) * 128; }
        else               { const int t = bx - 640; mode = 2; bn = (t & 3) * 128; bm = (t >> 2) * 128; }
    } else { mode = 3; bn = (blockIdx.x & 15) * 128; bm = (blockIdx.x >> 4) * 128; }

    const __half* Bm = (mode == 1) ? Bk : (mode == 2) ? Bv : Bq;
    const float* bias = (mode == 1) ? bias_k : (mode == 2) ? bias_v : bias_q;

    const int tid = threadIdx.x;
    const int warp = tid >> 5;
    const int lane = tid & 31;
    const int gid = lane >> 2;
    const int tig = lane & 3;
    const int warp_m = warp >> 2;
    const int warp_n = warp & 3;
    const int r8 = lane & 7;
    const int qd = lane >> 3;       // ldmatrix quadrant

    auto load_stage = [&](int s, int kc) {
        const uint32_t base = smb + (uint32_t)(s * GSTAGE_W) * 4u;
#pragma unroll
        for (int j = 0; j < 4; j++) {
            const int c = tid + 256 * j;       // 0..1023
            const int row = c >> 3;
            const int cc = c & 7;
            cpasync16(base + (row * GSTR + cc * 4) * 4,
                      A + (long)(bm + row) * DD + kc + cc * 8);
            cpasync16(base + (GTILE_W + row * GSTR + cc * 4) * 4,
                      Bm + (long)(bn + row) * DD + kc + cc * 8);
        }
        cp_commit();
    };

    float acc[4][4][4];
#pragma unroll
    for (int i = 0; i < 4; i++)
#pragma unroll
        for (int j = 0; j < 4; j++)
#pragma unroll
            for (int r = 0; r < 4; r++) acc[i][j][r] = 0.0f;

    const int a_row_l = warp_m * 64 + (qd & 1) * 8 + r8;
    const int a_col_l = (qd >> 1) * 4;
    const int b_row_l = warp_n * 32 + (qd >> 1) * 8 + r8;
    const int b_col_l = (qd & 1) * 4;

    const int nk = DD / 64;   // 32
    load_stage(0, 0);
    load_stage(1, 64);

#pragma unroll 1
    for (int i = 0; i < nk; ++i) {
        const int s = i % 3;
        if (i + 1 < nk) cp_wait<1>(); else cp_wait<0>();
        __syncthreads();
        if (i + 2 < nk) load_stage((i + 2) % 3, (i + 2) * 64);

        const uint32_t abase = smb + (uint32_t)(s * GSTAGE_W) * 4u;
        const uint32_t bbase = abase + (uint32_t)GTILE_W * 4u;

#pragma unroll
        for (int ks = 0; ks < 4; ks++) {
            uint32_t af[4][4], bf[4][2];
#pragma unroll
            for (int mt = 0; mt < 4; mt++)
                ldsm_x4(af[mt][0], af[mt][1], af[mt][2], af[mt][3],
                        abase + ((a_row_l + mt * 16) * GSTR + ks * 8 + a_col_l) * 4);
#pragma unroll
            for (int p = 0; p < 4; p += 2)
                ldsm_x4(bf[p][0], bf[p][1], bf[p + 1][0], bf[p + 1][1],
                        bbase + ((b_row_l + p * 8) * GSTR + ks * 8 + b_col_l) * 4);
#pragma unroll
            for (int mt = 0; mt < 4; mt++)
#pragma unroll
                for (int nt = 0; nt < 4; nt++)
                    mma_f16(acc[mt][nt], af[mt], bf[nt]);
        }
    }

    // epilogue
#pragma unroll
    for (int mt = 0; mt < 4; mt++) {
        const int r = bm + warp_m * 64 + mt * 16 + gid;
#pragma unroll
        for (int nt = 0; nt < 4; nt++) {
            const int c = bn + warp_n * 32 + nt * 8 + 2 * tig;
            const float bx0 = bias[c], bx1 = bias[c + 1];
            float v00 = acc[mt][nt][0] + bx0, v01 = acc[mt][nt][1] + bx1;
            float v10 = acc[mt][nt][2] + bx0, v11 = acc[mt][nt][3] + bx1;
            if (mode == 0) {          // Q: scale by log2e/8, fp16
                *(uint32_t*)(outq + (long)r * 2048 + c) =
                    pack_h2(v00 * QSCALE, v01 * QSCALE);
                *(uint32_t*)(outq + (long)(r + 8) * 2048 + c) =
                    pack_h2(v10 * QSCALE, v11 * QSCALE);
            } else if (mode == 1) {   // K: fp16
                *(uint32_t*)(outk + (long)r * 512 + c) = pack_h2(v00, v01);
                *(uint32_t*)(outk + (long)(r + 8) * 512 + c) = pack_h2(v10, v11);
            } else if (mode == 2) {   // V: fp16 transposed [b][hk][d][L], via movmatrix
                const uint32_t tt = movm_t(pack_h2(v00, v01));
                const uint32_t tb = movm_t(pack_h2(v10, v11));
                const int d_col = bn + warp_n * 32 + nt * 8 + gid;
                const int hk = d_col >> 6, d = d_col & 63;
                const int rglob = bm + warp_m * 64 + mt * 16 + 2 * tig;
                const int bb = rglob >> 11, lrow = rglob & 2047;
                const long base = ((long)(bb * NHKV + hk) * HD + d) * LL + lrow;
                *(uint32_t*)(outvt + base) = tt;
                *(uint32_t*)(outvt + base + 8) = tb;
            } else {                  // O: fp32 out
                *(float2*)(outf + (long)r * 2048 + c) = make_float2(v00, v01);
                *(float2*)(outf + (long)(r + 8) * 2048 + c) = make_float2(v10, v11);
            }
        }
    }
}

// ---------------------------------------------------------------------------
// fp16 tensor-core flash attention (exp2 softmax, register P, l via ones-MMA).
// Block: 128 q rows x head x batch. 256 threads (8 warps), warp = 16 q rows.
// V smem has 72 d-rows: rows 0-63 = V, row 64 = ones (row-sum trick), 65-71 = 0.
// Ones-tile B-fragments are constant -> hoisted out of the mainloop.
// ---------------------------------------------------------------------------
#define ASTR 36                         // words per row (32 data + 4 pad)
#define KT_W  (64 * ASTR)               // 2304 words per K buffer
#define KT_WV (72 * ASTR)               // 2592 words per V buffer
#define ATT_SMEM ((2 * KT_W + 2 * KT_WV) * 4)   // 39168 B
#define NKT (LL / 64)

__global__ __launch_bounds__(256, 2) void attn_f16(
    const __half* __restrict__ q, const __half* __restrict__ k,
    const __half* __restrict__ vt, __half* __restrict__ ctx)
{
    extern __shared__ uint32_t smw[];
    uint32_t* KsW = smw;                 // 2 x [64][36]
    uint32_t* VsW = smw + 2 * KT_W;      // 2 x [72][36]
    const uint32_t ks_s = (uint32_t)__cvta_generic_to_shared(KsW);
    const uint32_t vs_s = (uint32_t)__cvta_generic_to_shared(VsW);

    const int tid = threadIdx.x;
    const int warp = tid >> 5;
    const int lane = tid & 31;
    const int gid = lane >> 2;
    const int tig = lane & 3;
    const int r8 = lane & 7;
    const int qd = lane >> 3;
    const int qt = blockIdx.x;
    const int h  = blockIdx.y;
    const int b  = blockIdx.z;
    const int hk = h >> 2;
    const int qbase = qt * 128;

    const int bt_row = (qd >> 1) * 8 + r8;
    const int bt_col = (qd & 1) * 4;
    const int o_row = 64 + r8;
    const int o_col = ((lane >> 3) & 1) * 4;

    // static V rows 64-71: row 64 = 1.0h pairs, rows 65-71 = 0 (both buffers)
    for (int idx = tid; idx < 2 * 8 * ASTR; idx += 256) {
        const int bufi = idx / (8 * ASTR);
        const int rem = idx % (8 * ASTR);
        const int row = 64 + rem / ASTR;
        const int wcol = rem % ASTR;
        VsW[bufi * KT_WV + row * ASTR + wcol] = (row == 64) ? 0x3C003C00u : 0u;
    }
    __syncthreads();

    // hoist constant ones-tile B-fragments (identical in both buffers, all kt)
    uint32_t v8c[4][2];
#pragma unroll
    for (int ks = 0; ks < 4; ks++)
        ldsm_x2(v8c[ks][0], v8c[ks][1], vs_s + (uint32_t)(o_row * ASTR + ks * 8 + o_col) * 4);

    // Q fragments (fp16, pre-scaled by log2e/8). 4 k16-steps over HD=64.
    uint32_t qf[4][4];
    {
        const __half* qp = q + (long)(b * LL + qbase + warp * 16 + gid) * (NHQ * HD) + h * HD;
        const __half* qp8 = qp + (long)8 * (NHQ * HD);
#pragma unroll
        for (int ks = 0; ks < 4; ks++) {
            const int c = ks * 16 + 2 * tig;
            qf[ks][0] = *(const uint32_t*)(qp + c);
            qf[ks][1] = *(const uint32_t*)(qp8 + c);
            qf[ks][2] = *(const uint32_t*)(qp + c + 8);
            qf[ks][3] = *(const uint32_t*)(qp8 + c + 8);
        }
    }

    float o[8][4];
    float o8[4];
    float m[2];
#pragma unroll
    for (int nt = 0; nt < 8; nt++)
#pragma unroll
        for (int r = 0; r < 4; r++) o[nt][r] = 0.0f;
#pragma unroll
    for (int r = 0; r < 4; r++) o8[r] = 0.0f;
    m[0] = m[1] = -1e30f;

    const __half* kbase = k + (long)(b * LL) * (NHKV * HD) + hk * HD;
    const __half* vbase = vt + (long)(b * NHKV + hk) * HD * LL;

    auto load_kv = [&](int buf, int kt) {
#pragma unroll
        for (int j = 0; j < 2; j++) {
            const int c = tid + 256 * j;
            const int row = c >> 3;
            const int cc = c & 7;
            cpasync16(ks_s + ((buf * KT_W) + row * ASTR + cc * 4) * 4,
                      kbase + (long)(kt * 64 + row) * (NHKV * HD) + cc * 8);
            cpasync16(vs_s + ((buf * KT_WV) + row * ASTR + cc * 4) * 4,
                      vbase + (long)row * LL + kt * 64 + cc * 8);
        }
        cp_commit();
    };

    load_kv(0, 0);

#pragma unroll 1
    for (int kt = 0; kt < NKT; kt++) {
        const int buf = kt & 1;
        cp_wait<0>();
        __syncthreads();
        if (kt + 1 < NKT) load_kv(buf ^ 1, kt + 1);

        const uint32_t kb = ks_s + (uint32_t)(buf * KT_W) * 4u;
        const uint32_t vb = vs_s + (uint32_t)(buf * KT_WV) * 4u;

        // ---- S = Q @ K^T (log2 domain) ----
        float sacc[8][4];
#pragma unroll
        for (int nt = 0; nt < 8; nt++)
#pragma unroll
            for (int r = 0; r < 4; r++) sacc[nt][r] = 0.0f;

#pragma unroll
        for (int ks = 0; ks < 4; ks++) {
            uint32_t bf[8][2];
#pragma unroll
            for (int p = 0; p < 8; p += 2)
                ldsm_x4(bf[p][0], bf[p][1], bf[p + 1][0], bf[p + 1][1],
                        kb + ((p * 8 + bt_row) * ASTR + ks * 8 + bt_col) * 4);
#pragma unroll
            for (int nt = 0; nt < 8; nt++)
                mma_f16(sacc[nt], qf[ks], bf[nt]);
        }

        // ---- online softmax (exp2); P into A-frag registers ----
        uint32_t ph[8][2];
#pragma unroll
        for (int i = 0; i < 2; i++) {
            const int r0 = 2 * i;
            float tm = -1e30f;
#pragma unroll
            for (int nt = 0; nt < 8; nt++)
                tm = fmaxf(tm, fmaxf(sacc[nt][r0], sacc[nt][r0 + 1]));
            tm = fmaxf(tm, __shfl_xor_sync(0xffffffffu, tm, 1));
            tm = fmaxf(tm, __shfl_xor_sync(0xffffffffu, tm, 2));
            const float mn = fmaxf(m[i], tm);
            const float alpha = ex2f(m[i] - mn);
            m[i] = mn;
#pragma unroll
            for (int nt = 0; nt < 8; nt++) {
                float p0 = ex2f(sacc[nt][r0] - mn);
                float p1 = ex2f(sacc[nt][r0 + 1] - mn);
                ph[nt][i] = pack_h2(p0, p1);
            }
#pragma unroll
            for (int nt = 0; nt < 8; nt++) {
                o[nt][r0]     *= alpha;
                o[nt][r0 + 1] *= alpha;
            }
            o8[r0]     *= alpha;
            o8[r0 + 1] *= alpha;
        }

        // ---- O += P @ V (P register-resident; +constant ones column for l) ----
#pragma unroll
        for (int ks = 0; ks < 4; ks++) {
            uint32_t vf[8][2];
            uint32_t pf[4] = { ph[2 * ks][0], ph[2 * ks][1],
                               ph[2 * ks + 1][0], ph[2 * ks + 1][1] };
#pragma unroll
            for (int p = 0; p < 8; p += 2)
                ldsm_x4(vf[p][0], vf[p][1], vf[p + 1][0], vf[p + 1][1],
                        vb + ((p * 8 + bt_row) * ASTR + ks * 8 + bt_col) * 4);
#pragma unroll
            for (int nt = 0; nt < 8; nt++)
                mma_f16(o[nt], pf, vf[nt]);
            mma_f16(o8, pf, v8c[ks]);
        }
    }

    // ---- recover l, normalize + fp16 store ----
    {
        const int src = lane & ~3;
        const float l0 = __shfl_sync(0xffffffffu, o8[0], src);
        const float l1 = __shfl_sync(0xffffffffu, o8[2], src);
        const float inv0 = 1.0f / l0;
        const float inv1 = 1.0f / l1;
        __half* cp0 = ctx + (long)(b * LL + qbase + warp * 16 + gid) * (NHQ * HD) + h * HD;
        __half* cp1 = cp0 + (long)8 * (NHQ * HD);
#pragma unroll
        for (int nt = 0; nt < 8; nt++) {
            const int c0 = nt * 8 + 2 * tig;
            *(uint32_t*)(cp0 + c0) = pack_h2(o[nt][0] * inv0, o[nt][1] * inv0);
            *(uint32_t*)(cp1 + c0) = pack_h2(o[nt][2] * inv1, o[nt][3] * inv1);
        }
    }
}

// ---------------------------------------------------------------------------
extern "C" void kernel_launch(void* const* d_in, const int* in_sizes, int n_in,
                              void* d_out, int out_size)
{
    const float* x  = (const float*)d_in[0];
    const float* Wq = (const float*)d_in[1];
    const float* bq = (const float*)d_in[2];
    const float* Wk = (const float*)d_in[3];
    const float* bk = (const float*)d_in[4];
    const float* Wv = (const float*)d_in[5];
    const float* bv = (const float*)d_in[6];
    const float* Wo = (const float*)d_in[7];
    const float* bo = (const float*)d_in[8];
    float* out = (float*)d_out;

    __half *gxh, *gwqt, *gwkt, *gwvt, *gwot, *gq, *gk, *gvt, *gctx;
    cudaGetSymbolAddress((void**)&gxh, g_xh);
    cudaGetSymbolAddress((void**)&gwqt, g_wqt);
    cudaGetSymbolAddress((void**)&gwkt, g_wkt);
    cudaGetSymbolAddress((void**)&gwvt, g_wvt);
    cudaGetSymbolAddress((void**)&gwot, g_wot);
    cudaGetSymbolAddress((void**)&gq, g_q);
    cudaGetSymbolAddress((void**)&gk, g_k);
    cudaGetSymbolAddress((void**)&gvt, g_vt);
    cudaGetSymbolAddress((void**)&gctx, g_ctx);

    const int M = BB * LL;   // 4096

    cudaFuncSetAttribute(gemm_f16, cudaFuncAttributeMaxDynamicSharedMemorySize, GSMEM);
    cudaFuncSetAttribute(attn_f16, cudaFuncAttributeMaxDynamicSharedMemorySize, ATT_SMEM);

    // prep needed for QKV (Wo transpose deferred past attention)
    {
        const int nx = M * DD;
        cvt_h_kernel<<<nx / 1024, 256>>>(x, gxh, nx);
        dim3 blk(32, 8);
        transpose_h_kernel<<<dim3((NHQ * HD) / 32, DD / 32, 1), blk>>>(
            Wq, Wq, gwqt, gwqt, DD, NHQ * HD);
        transpose_h_kernel<<<dim3((NHKV * HD) / 32, DD / 32, 2), blk>>>(
            Wk, Wv, gwkt, gwvt, DD, NHKV * HD);
    }

    // fused QKV projections
    gemm_f16<<<768, 256, GSMEM>>>(gxh, gwqt, gwkt, gwvt, bq, bk, bv,
                                  gq, gk, gvt, out, 1);

    // attention
    {
        dim3 grid(LL / 128, NHQ, BB);
        attn_f16<<<grid, 256, ATT_SMEM>>>(gq, gk, gvt, gctx);
    }

    // Wo transpose (only needed by O projection)
    {
        dim3 blk(32, 8);
        transpose_h_kernel<<<dim3(DD / 32, (NHQ * HD) / 32, 1), blk>>>(
            Wo, Wo, gwot, gwot, NHQ * HD, DD);
    }

    // O projection (fp32 out)
    gemm_f16<<<512, 256, GSMEM>>>(gctx, gwot, gwot, gwot, bo, bo, bo,
                                  gq, gk, gvt, out, 0);
}

// round 15
// speedup vs baseline: 1.0217x; 1.0217x over previous
#include <cuda_runtime.h>
#include <cuda_fp16.h>
#include <cstdint>
#include <math.h>

// Problem constants
#define BB   2
#define LL   2048
#define DD   2048
#define NHQ  32
#define NHKV 8
#define HD   64
#define GRP  4

// ---------------------------------------------------------------------------
// Scratch (allocation-free rule: __device__ globals)
// ---------------------------------------------------------------------------
__device__ __half g_xh[BB * LL * DD];              // x fp16
__device__ __half g_wqt[NHQ * HD * DD];            // Wq^T [N][K]
__device__ __half g_wkt[NHKV * HD * DD];
__device__ __half g_wvt[NHKV * HD * DD];
__device__ __half g_wot[DD * NHQ * HD];
__device__ __half g_q[BB * LL * NHQ * HD];         // q fp16 (pre-scaled by log2e/8)
__device__ __half g_k[BB * LL * NHKV * HD];        // k fp16
__device__ __half g_vt[BB * NHKV * HD * LL];       // v fp16, [b][hk][d][L]
__device__ __half g_ctx[BB * LL * NHQ * HD];       // attention output fp16

// ---------------------------------------------------------------------------
// helpers
// ---------------------------------------------------------------------------
__device__ __forceinline__ void mma_f16(float* d, const uint32_t* a, const uint32_t* b) {
    asm volatile(
        "mma.sync.aligned.m16n8k16.row.col.f32.f16.f16.f32 "
        "{%0,%1,%2,%3}, {%4,%5,%6,%7}, {%8,%9}, {%0,%1,%2,%3};"
        : "+f"(d[0]), "+f"(d[1]), "+f"(d[2]), "+f"(d[3])
        : "r"(a[0]), "r"(a[1]), "r"(a[2]), "r"(a[3]), "r"(b[0]), "r"(b[1]));
}

// pack two f32 into one f16x2 register (lo = a, hi = b)
__device__ __forceinline__ uint32_t pack_h2(float a, float b) {
    uint32_t r;
    asm("cvt.rn.f16x2.f32 %0, %1, %2;" : "=r"(r) : "f"(b), "f"(a));
    return r;
}

// explicit fast exp2 (MUFU.EX2)
__device__ __forceinline__ float ex2f(float x) {
    float y;
    asm("ex2.approx.f32 %0, %1;" : "=f"(y) : "f"(x));
    return y;
}

// in-register 8x8 fp16 tile transpose (warp-collective)
__device__ __forceinline__ uint32_t movm_t(uint32_t a) {
    uint32_t d;
    asm("movmatrix.sync.aligned.m8n8.trans.b16 %0, %1;" : "=r"(d) : "r"(a));
    return d;
}

// ldmatrix x4: 4 8x8 fp16 tiles
__device__ __forceinline__ void ldsm_x4(uint32_t& r0, uint32_t& r1, uint32_t& r2,
                                        uint32_t& r3, uint32_t addr) {
    asm volatile("ldmatrix.sync.aligned.m8n8.x4.shared.b16 {%0,%1,%2,%3}, [%4];"
                 : "=r"(r0), "=r"(r1), "=r"(r2), "=r"(r3) : "r"(addr));
}

// ldmatrix x2
__device__ __forceinline__ void ldsm_x2(uint32_t& r0, uint32_t& r1, uint32_t addr) {
    asm volatile("ldmatrix.sync.aligned.m8n8.x2.shared.b16 {%0,%1}, [%2];"
                 : "=r"(r0), "=r"(r1) : "r"(addr));
}

__device__ __forceinline__ void cpasync16(uint32_t saddr, const void* g) {
    asm volatile("cp.async.cg.shared.global [%0], [%1], 16;\n" :: "r"(saddr), "l"(g) : "memory");
}
__device__ __forceinline__ void cp_commit() {
    asm volatile("cp.async.commit_group;\n" ::: "memory");
}
template <int N>
__device__ __forceinline__ void cp_wait() {
    asm volatile("cp.async.wait_group %0;\n" :: "n"(N) : "memory");
}

// ---------------------------------------------------------------------------
// prep: x -> fp16, 4 float4 per thread (grid-strided, coalesced, MLP=4)
// ---------------------------------------------------------------------------
__global__ __launch_bounds__(256) void cvt_h_kernel(
    const float* __restrict__ in, __half* __restrict__ out, int n)
{
    const int stride = gridDim.x * 256 * 4;
#pragma unroll
    for (int j = 0; j < 4; j++) {
        const int i = (blockIdx.x * 256 + threadIdx.x) * 4 + j * stride;
        if (i < n) {
            float4 v = *(const float4*)(in + i);
            uint32_t h0 = pack_h2(v.x, v.y);
            uint32_t h1 = pack_h2(v.z, v.w);
            *(uint32_t*)(out + i) = h0;
            *(uint32_t*)(out + i + 2) = h1;
        }
    }
}

// ---------------------------------------------------------------------------
// prep: transpose W[K,N] -> WT[N,K] fp16 (z-dim selects tensor pair)
// ---------------------------------------------------------------------------
__global__ __launch_bounds__(256) void transpose_h_kernel(
    const float* __restrict__ W0, const float* __restrict__ W1,
    __half* __restrict__ T0, __half* __restrict__ T1, int K, int N)
{
    __shared__ float t[32][33];
    const float* W = blockIdx.z ? W1 : W0;
    __half* T = blockIdx.z ? T1 : T0;
    const int n0 = blockIdx.x * 32;
    const int k0 = blockIdx.y * 32;
    const int tx = threadIdx.x, ty = threadIdx.y;
#pragma unroll
    for (int i = 0; i < 4; i++)
        t[ty + i * 8][tx] = W[(long)(k0 + ty + i * 8) * N + n0 + tx];
    __syncthreads();
#pragma unroll
    for (int i = 0; i < 4; i++)
        T[(long)(n0 + ty + i * 8) * K + k0 + tx] = __float2half(t[tx][ty + i * 8]);
}

// ---------------------------------------------------------------------------
// fp16 tensor-core GEMM: C[M,N] = A[M,K] @ BT[N,K]^T + bias
// 128x128 tile, K-chunk 64, 3-stage cp.async, 256 threads, warp tile 64x32,
// 2 CTAs/SM. (Proven Round-12 config.)
// ---------------------------------------------------------------------------
#define GSTR    36                 // 32-bit words per row (32 data + 4 pad)
#define GTILE_W (128 * GSTR)       // 4608 words per operand tile
#define GSTAGE_W (2 * GTILE_W)     // 9216 words = 36 KB
#define GSMEM   (3 * GSTAGE_W * 4) // 110592 B

#define QSCALE 0.1803368867f       // 0.125 * log2(e)

__global__ __launch_bounds__(256, 2) void gemm_f16(
    const __half* __restrict__ A,
    const __half* __restrict__ Bq, const __half* __restrict__ Bk,
    const __half* __restrict__ Bv,
    const float* __restrict__ bias_q, const float* __restrict__ bias_k,
    const float* __restrict__ bias_v,
    __half* __restrict__ outq, __half* __restrict__ outk,
    __half* __restrict__ outvt, float* __restrict__ outf,
    int qkv_mode)
{
    extern __shared__ uint32_t smw[];
    const uint32_t smb = (uint32_t)__cvta_generic_to_shared(smw);

    int mode, bm, bn;
    if (qkv_mode) {
        const int bx = blockIdx.x;
        if (bx < 512)      { mode = 0; bn = (bx & 15) * 128; bm = (bx >> 4) * 128; }
        else if (bx < 640) { const int t = bx - 512; mode = 1; bn = (t & 3) * 128; bm = (t >> 2) * 128; }
        else               { const int t = bx - 640; mode = 2; bn = (t & 3) * 128; bm = (t >> 2) * 128; }
    } else { mode = 3; bn = (blockIdx.x & 15) * 128; bm = (blockIdx.x >> 4) * 128; }

    const __half* Bm = (mode == 1) ? Bk : (mode == 2) ? Bv : Bq;
    const float* bias = (mode == 1) ? bias_k : (mode == 2) ? bias_v : bias_q;

    const int tid = threadIdx.x;
    const int warp = tid >> 5;
    const int lane = tid & 31;
    const int gid = lane >> 2;
    const int tig = lane & 3;
    const int warp_m = warp >> 2;
    const int warp_n = warp & 3;
    const int r8 = lane & 7;
    const int qd = lane >> 3;       // ldmatrix quadrant

    auto load_stage = [&](int s, int kc) {
        const uint32_t base = smb + (uint32_t)(s * GSTAGE_W) * 4u;
#pragma unroll
        for (int j = 0; j < 4; j++) {
            const int c = tid + 256 * j;       // 0..1023
            const int row = c >> 3;
            const int cc = c & 7;
            cpasync16(base + (row * GSTR + cc * 4) * 4,
                      A + (long)(bm + row) * DD + kc + cc * 8);
            cpasync16(base + (GTILE_W + row * GSTR + cc * 4) * 4,
                      Bm + (long)(bn + row) * DD + kc + cc * 8);
        }
        cp_commit();
    };

    float acc[4][4][4];
#pragma unroll
    for (int i = 0; i < 4; i++)
#pragma unroll
        for (int j = 0; j < 4; j++)
#pragma unroll
            for (int r = 0; r < 4; r++) acc[i][j][r] = 0.0f;

    const int a_row_l = warp_m * 64 + (qd & 1) * 8 + r8;
    const int a_col_l = (qd >> 1) * 4;
    const int b_row_l = warp_n * 32 + (qd >> 1) * 8 + r8;
    const int b_col_l = (qd & 1) * 4;

    const int nk = DD / 64;   // 32
    load_stage(0, 0);
    load_stage(1, 64);

#pragma unroll 1
    for (int i = 0; i < nk; ++i) {
        const int s = i % 3;
        if (i + 1 < nk) cp_wait<1>(); else cp_wait<0>();
        __syncthreads();
        if (i + 2 < nk) load_stage((i + 2) % 3, (i + 2) * 64);

        const uint32_t abase = smb + (uint32_t)(s * GSTAGE_W) * 4u;
        const uint32_t bbase = abase + (uint32_t)GTILE_W * 4u;

#pragma unroll
        for (int ks = 0; ks < 4; ks++) {
            uint32_t af[4][4], bf[4][2];
#pragma unroll
            for (int mt = 0; mt < 4; mt++)
                ldsm_x4(af[mt][0], af[mt][1], af[mt][2], af[mt][3],
                        abase + ((a_row_l + mt * 16) * GSTR + ks * 8 + a_col_l) * 4);
#pragma unroll
            for (int p = 0; p < 4; p += 2)
                ldsm_x4(bf[p][0], bf[p][1], bf[p + 1][0], bf[p + 1][1],
                        bbase + ((b_row_l + p * 8) * GSTR + ks * 8 + b_col_l) * 4);
#pragma unroll
            for (int mt = 0; mt < 4; mt++)
#pragma unroll
                for (int nt = 0; nt < 4; nt++)
                    mma_f16(acc[mt][nt], af[mt], bf[nt]);
        }
    }

    // epilogue
#pragma unroll
    for (int mt = 0; mt < 4; mt++) {
        const int r = bm + warp_m * 64 + mt * 16 + gid;
#pragma unroll
        for (int nt = 0; nt < 4; nt++) {
            const int c = bn + warp_n * 32 + nt * 8 + 2 * tig;
            const float bx0 = bias[c], bx1 = bias[c + 1];
            float v00 = acc[mt][nt][0] + bx0, v01 = acc[mt][nt][1] + bx1;
            float v10 = acc[mt][nt][2] + bx0, v11 = acc[mt][nt][3] + bx1;
            if (mode == 0) {          // Q: scale by log2e/8, fp16
                *(uint32_t*)(outq + (long)r * 2048 + c) =
                    pack_h2(v00 * QSCALE, v01 * QSCALE);
                *(uint32_t*)(outq + (long)(r + 8) * 2048 + c) =
                    pack_h2(v10 * QSCALE, v11 * QSCALE);
            } else if (mode == 1) {   // K: fp16
                *(uint32_t*)(outk + (long)r * 512 + c) = pack_h2(v00, v01);
                *(uint32_t*)(outk + (long)(r + 8) * 512 + c) = pack_h2(v10, v11);
            } else if (mode == 2) {   // V: fp16 transposed [b][hk][d][L], via movmatrix
                const uint32_t tt = movm_t(pack_h2(v00, v01));
                const uint32_t tb = movm_t(pack_h2(v10, v11));
                const int d_col = bn + warp_n * 32 + nt * 8 + gid;
                const int hk = d_col >> 6, d = d_col & 63;
                const int rglob = bm + warp_m * 64 + mt * 16 + 2 * tig;
                const int bb = rglob >> 11, lrow = rglob & 2047;
                const long base = ((long)(bb * NHKV + hk) * HD + d) * LL + lrow;
                *(uint32_t*)(outvt + base) = tt;
                *(uint32_t*)(outvt + base + 8) = tb;
            } else {                  // O: fp32 out
                *(float2*)(outf + (long)r * 2048 + c) = make_float2(v00, v01);
                *(float2*)(outf + (long)(r + 8) * 2048 + c) = make_float2(v10, v11);
            }
        }
    }
}

// ---------------------------------------------------------------------------
// fp16 tensor-core flash attention (exp2 softmax, register P, l via ones-MMA).
// Block: 128 q rows x head x batch. 256 threads (8 warps), warp = 16 q rows.
// V smem has 72 d-rows: rows 0-63 = V, row 64 = ones (row-sum trick), 65-71 = 0.
// ---------------------------------------------------------------------------
#define ASTR 36                         // words per row (32 data + 4 pad)
#define KT_W  (64 * ASTR)               // 2304 words per K buffer
#define KT_WV (72 * ASTR)               // 2592 words per V buffer
#define ATT_SMEM ((2 * KT_W + 2 * KT_WV) * 4)   // 39168 B
#define NKT (LL / 64)

__global__ __launch_bounds__(256, 2) void attn_f16(
    const __half* __restrict__ q, const __half* __restrict__ k,
    const __half* __restrict__ vt, __half* __restrict__ ctx)
{
    extern __shared__ uint32_t smw[];
    uint32_t* KsW = smw;                 // 2 x [64][36]
    uint32_t* VsW = smw + 2 * KT_W;      // 2 x [72][36]
    const uint32_t ks_s = (uint32_t)__cvta_generic_to_shared(KsW);
    const uint32_t vs_s = (uint32_t)__cvta_generic_to_shared(VsW);

    const int tid = threadIdx.x;
    const int warp = tid >> 5;
    const int lane = tid & 31;
    const int gid = lane >> 2;
    const int tig = lane & 3;
    const int r8 = lane & 7;
    const int qd = lane >> 3;
    const int qt = blockIdx.x;
    const int h  = blockIdx.y;
    const int b  = blockIdx.z;
    const int hk = h >> 2;
    const int qbase = qt * 128;

    const int bt_row = (qd >> 1) * 8 + r8;
    const int bt_col = (qd & 1) * 4;
    const int o_row = 64 + r8;
    const int o_col = ((lane >> 3) & 1) * 4;

    // static V rows 64-71: row 64 = 1.0h pairs, rows 65-71 = 0 (both buffers)
    for (int idx = tid; idx < 2 * 8 * ASTR; idx += 256) {
        const int bufi = idx / (8 * ASTR);
        const int rem = idx % (8 * ASTR);
        const int row = 64 + rem / ASTR;
        const int wcol = rem % ASTR;
        VsW[bufi * KT_WV + row * ASTR + wcol] = (row == 64) ? 0x3C003C00u : 0u;
    }

    // Q fragments (fp16, pre-scaled by log2e/8). 4 k16-steps over HD=64.
    uint32_t qf[4][4];
    {
        const __half* qp = q + (long)(b * LL + qbase + warp * 16 + gid) * (NHQ * HD) + h * HD;
        const __half* qp8 = qp + (long)8 * (NHQ * HD);
#pragma unroll
        for (int ks = 0; ks < 4; ks++) {
            const int c = ks * 16 + 2 * tig;
            qf[ks][0] = *(const uint32_t*)(qp + c);
            qf[ks][1] = *(const uint32_t*)(qp8 + c);
            qf[ks][2] = *(const uint32_t*)(qp + c + 8);
            qf[ks][3] = *(const uint32_t*)(qp8 + c + 8);
        }
    }

    float o[8][4];
    float o8[4];
    float m[2];
#pragma unroll
    for (int nt = 0; nt < 8; nt++)
#pragma unroll
        for (int r = 0; r < 4; r++) o[nt][r] = 0.0f;
#pragma unroll
    for (int r = 0; r < 4; r++) o8[r] = 0.0f;
    m[0] = m[1] = -1e30f;

    const __half* kbase = k + (long)(b * LL) * (NHKV * HD) + hk * HD;
    const __half* vbase = vt + (long)(b * NHKV + hk) * HD * LL;

    auto load_kv = [&](int buf, int kt) {
#pragma unroll
        for (int j = 0; j < 2; j++) {
            const int c = tid + 256 * j;
            const int row = c >> 3;
            const int cc = c & 7;
            cpasync16(ks_s + ((buf * KT_W) + row * ASTR + cc * 4) * 4,
                      kbase + (long)(kt * 64 + row) * (NHKV * HD) + cc * 8);
            cpasync16(vs_s + ((buf * KT_WV) + row * ASTR + cc * 4) * 4,
                      vbase + (long)row * LL + kt * 64 + cc * 8);
        }
        cp_commit();
    };

    load_kv(0, 0);

#pragma unroll 1
    for (int kt = 0; kt < NKT; kt++) {
        const int buf = kt & 1;
        cp_wait<0>();
        __syncthreads();
        if (kt + 1 < NKT) load_kv(buf ^ 1, kt + 1);

        const uint32_t kb = ks_s + (uint32_t)(buf * KT_W) * 4u;
        const uint32_t vb = vs_s + (uint32_t)(buf * KT_WV) * 4u;

        // ---- S = Q @ K^T (log2 domain) ----
        float sacc[8][4];
#pragma unroll
        for (int nt = 0; nt < 8; nt++)
#pragma unroll
            for (int r = 0; r < 4; r++) sacc[nt][r] = 0.0f;

#pragma unroll
        for (int ks = 0; ks < 4; ks++) {
            uint32_t bf[8][2];
#pragma unroll
            for (int p = 0; p < 8; p += 2)
                ldsm_x4(bf[p][0], bf[p][1], bf[p + 1][0], bf[p + 1][1],
                        kb + ((p * 8 + bt_row) * ASTR + ks * 8 + bt_col) * 4);
#pragma unroll
            for (int nt = 0; nt < 8; nt++)
                mma_f16(sacc[nt], qf[ks], bf[nt]);
        }

        // ---- online softmax (exp2); P into A-frag registers ----
        uint32_t ph[8][2];
#pragma unroll
        for (int i = 0; i < 2; i++) {
            const int r0 = 2 * i;
            float tm = -1e30f;
#pragma unroll
            for (int nt = 0; nt < 8; nt++)
                tm = fmaxf(tm, fmaxf(sacc[nt][r0], sacc[nt][r0 + 1]));
            tm = fmaxf(tm, __shfl_xor_sync(0xffffffffu, tm, 1));
            tm = fmaxf(tm, __shfl_xor_sync(0xffffffffu, tm, 2));
            const float mn = fmaxf(m[i], tm);
            const float alpha = ex2f(m[i] - mn);
            m[i] = mn;
#pragma unroll
            for (int nt = 0; nt < 8; nt++) {
                float p0 = ex2f(sacc[nt][r0] - mn);
                float p1 = ex2f(sacc[nt][r0 + 1] - mn);
                ph[nt][i] = pack_h2(p0, p1);
            }
#pragma unroll
            for (int nt = 0; nt < 8; nt++) {
                o[nt][r0]     *= alpha;
                o[nt][r0 + 1] *= alpha;
            }
            o8[r0]     *= alpha;
            o8[r0 + 1] *= alpha;
        }

        // ---- O += P @ V (P register-resident; +ones column for l) ----
#pragma unroll
        for (int ks = 0; ks < 4; ks++) {
            uint32_t vf[8][2];
            uint32_t pf[4] = { ph[2 * ks][0], ph[2 * ks][1],
                               ph[2 * ks + 1][0], ph[2 * ks + 1][1] };
#pragma unroll
            for (int p = 0; p < 8; p += 2)
                ldsm_x4(vf[p][0], vf[p][1], vf[p + 1][0], vf[p + 1][1],
                        vb + ((p * 8 + bt_row) * ASTR + ks * 8 + bt_col) * 4);
#pragma unroll
            for (int nt = 0; nt < 8; nt++)
                mma_f16(o[nt], pf, vf[nt]);
            uint32_t v8[2];
            ldsm_x2(v8[0], v8[1], vb + (o_row * ASTR + ks * 8 + o_col) * 4);
            mma_f16(o8, pf, v8);
        }
    }

    // ---- recover l, normalize + fp16 store ----
    {
        const int src = lane & ~3;
        const float l0 = __shfl_sync(0xffffffffu, o8[0], src);
        const float l1 = __shfl_sync(0xffffffffu, o8[2], src);
        const float inv0 = 1.0f / l0;
        const float inv1 = 1.0f / l1;
        __half* cp0 = ctx + (long)(b * LL + qbase + warp * 16 + gid) * (NHQ * HD) + h * HD;
        __half* cp1 = cp0 + (long)8 * (NHQ * HD);
#pragma unroll
        for (int nt = 0; nt < 8; nt++) {
            const int c0 = nt * 8 + 2 * tig;
            *(uint32_t*)(cp0 + c0) = pack_h2(o[nt][0] * inv0, o[nt][1] * inv0);
            *(uint32_t*)(cp1 + c0) = pack_h2(o[nt][2] * inv1, o[nt][3] * inv1);
        }
    }
}

// ---------------------------------------------------------------------------
extern "C" void kernel_launch(void* const* d_in, const int* in_sizes, int n_in,
                              void* d_out, int out_size)
{
    const float* x  = (const float*)d_in[0];
    const float* Wq = (const float*)d_in[1];
    const float* bq = (const float*)d_in[2];
    const float* Wk = (const float*)d_in[3];
    const float* bk = (const float*)d_in[4];
    const float* Wv = (const float*)d_in[5];
    const float* bv = (const float*)d_in[6];
    const float* Wo = (const float*)d_in[7];
    const float* bo = (const float*)d_in[8];
    float* out = (float*)d_out;

    __half *gxh, *gwqt, *gwkt, *gwvt, *gwot, *gq, *gk, *gvt, *gctx;
    cudaGetSymbolAddress((void**)&gxh, g_xh);
    cudaGetSymbolAddress((void**)&gwqt, g_wqt);
    cudaGetSymbolAddress((void**)&gwkt, g_wkt);
    cudaGetSymbolAddress((void**)&gwvt, g_wvt);
    cudaGetSymbolAddress((void**)&gwot, g_wot);
    cudaGetSymbolAddress((void**)&gq, g_q);
    cudaGetSymbolAddress((void**)&gk, g_k);
    cudaGetSymbolAddress((void**)&gvt, g_vt);
    cudaGetSymbolAddress((void**)&gctx, g_ctx);

    const int M = BB * LL;   // 4096

    cudaFuncSetAttribute(gemm_f16, cudaFuncAttributeMaxDynamicSharedMemorySize, GSMEM);
    cudaFuncSetAttribute(attn_f16, cudaFuncAttributeMaxDynamicSharedMemorySize, ATT_SMEM);

    // one-time side streams + events (no device memory; created outside capture
    // on the correctness call, reused under graph capture afterwards)
    static cudaStream_t sA = nullptr, sB = nullptr;
    static cudaEvent_t eRoot, eQ, eW, eKV;
    if (!sA) {
        cudaStreamCreateWithFlags(&sA, cudaStreamNonBlocking);
        cudaStreamCreateWithFlags(&sB, cudaStreamNonBlocking);
        cudaEventCreateWithFlags(&eRoot, cudaEventDisableTiming);
        cudaEventCreateWithFlags(&eQ, cudaEventDisableTiming);
        cudaEventCreateWithFlags(&eW, cudaEventDisableTiming);
        cudaEventCreateWithFlags(&eKV, cudaEventDisableTiming);
    }

    dim3 tblk(32, 8);

    // fork: prep runs on 3 streams concurrently
    cudaEventRecord(eRoot, 0);
    cudaStreamWaitEvent(sA, eRoot, 0);
    cudaStreamWaitEvent(sB, eRoot, 0);

    // main stream: x -> fp16 (4 float4 per thread)
    {
        const int nx = M * DD;
        cvt_h_kernel<<<nx / 4096, 256>>>(x, gxh, nx);
    }
    // sA: Wq transpose, then Wo transpose (Wo only needed by O-proj)
    transpose_h_kernel<<<dim3((NHQ * HD) / 32, DD / 32, 1), tblk, 0, sA>>>(
        Wq, Wq, gwqt, gwqt, DD, NHQ * HD);
    cudaEventRecord(eQ, sA);
    transpose_h_kernel<<<dim3(DD / 32, (NHQ * HD) / 32, 1), tblk, 0, sA>>>(
        Wo, Wo, gwot, gwot, NHQ * HD, DD);
    cudaEventRecord(eW, sA);
    // sB: Wk + Wv transposes fused
    transpose_h_kernel<<<dim3((NHKV * HD) / 32, DD / 32, 2), tblk, 0, sB>>>(
        Wk, Wv, gwkt, gwvt, DD, NHKV * HD);
    cudaEventRecord(eKV, sB);

    // join for QKV (needs cvt + trQ + trKV; Wo transpose keeps running on sA)
    cudaStreamWaitEvent(0, eQ, 0);
    cudaStreamWaitEvent(0, eKV, 0);

    // fused QKV projections
    gemm_f16<<<768, 256, GSMEM>>>(gxh, gwqt, gwkt, gwvt, bq, bk, bv,
                                  gq, gk, gvt, out, 1);

    // attention (Wo transpose on sA overlaps with this)
    {
        dim3 grid(LL / 128, NHQ, BB);
        attn_f16<<<grid, 256, ATT_SMEM>>>(gq, gk, gvt, gctx);
    }

    // join Wo transpose before O projection
    cudaStreamWaitEvent(0, eW, 0);

    // O projection (fp32 out)
    gemm_f16<<<512, 256, GSMEM>>>(gctx, gwot, gwot, gwot, bo, bo, bo,
                                  gq, gk, gvt, out, 0);
}